// round 1
// baseline (speedup 1.0000x reference)
#include <cuda_runtime.h>
#include <cstdint>

// ---------------------------------------------------------------------------
// HiPPO-LegT scan:  c_t = A c_{t-1} + f_t * B,  per (b,d) sequence.
// inputs: (16,128,512) f32; A: (64,64) f32; B: (64,) f32
// out:    (512, 16, 128, 64) f32  -> out[((t*2048)+bd)*64 + n]
//
// One warp per sequence. Thread `lane` owns output rows n0=2*lane, n0+1.
// A rows kept in registers as packed f32x2 pairs (over m). State c in shared,
// double buffered; read as 16B vector loads giving pre-packed (c[m],c[m+1])
// pairs in aligned 64-bit registers. Math via Blackwell packed fma.rn.f32x2.
// ---------------------------------------------------------------------------

__device__ __forceinline__ double fma2(double a, double b, double c) {
    double d;
    asm("fma.rn.f32x2 %0, %1, %2, %3;" : "=d"(d) : "d"(a), "d"(b), "d"(c));
    return d;
}
__device__ __forceinline__ double add2(double a, double b) {
    double d;
    asm("add.rn.f32x2 %0, %1, %2;" : "=d"(d) : "d"(a), "d"(b));
    return d;
}
__device__ __forceinline__ double pack2(float lo, float hi) {
    double d;
    asm("mov.b64 %0, {%1, %2};" : "=d"(d) : "f"(lo), "f"(hi));
    return d;
}
__device__ __forceinline__ void unpack2(double d, float& lo, float& hi) {
    asm("mov.b64 {%0, %1}, %2;" : "=f"(lo), "=f"(hi) : "d"(d));
}

static constexpr int SEQ_LEN  = 512;
static constexpr int NSTATE   = 64;
static constexpr int BD_TOTAL = 2048;   // 16 * 128

__global__ __launch_bounds__(32)
void hippo_scan_kernel(const float* __restrict__ xin,
                       const float* __restrict__ Amat,
                       const float* __restrict__ Bvec,
                       float* __restrict__ out)
{
    const int bd   = blockIdx.x;
    const int lane = threadIdx.x;
    const int n0   = 2 * lane;

    __shared__ __align__(16) double c_sm[2][NSTATE / 2];  // 64 f32 packed as 32 f32x2
    __shared__ float f_sm[SEQ_LEN];

    // Preload this sequence's 512 f values (broadcast-read later).
    {
        const float4* src = reinterpret_cast<const float4*>(xin + (size_t)bd * SEQ_LEN);
        float4* dst = reinterpret_cast<float4*>(f_sm);
        #pragma unroll
        for (int i = 0; i < SEQ_LEN / 4 / 32; i++)
            dst[lane + 32 * i] = src[lane + 32 * i];
    }

    // Preload A rows n0, n0+1 as packed f32 pairs (over m). 128 registers.
    double a0[NSTATE / 2], a1[NSTATE / 2];
    {
        const double* r0 = reinterpret_cast<const double*>(Amat + (size_t)n0 * NSTATE);
        const double* r1 = reinterpret_cast<const double*>(Amat + (size_t)(n0 + 1) * NSTATE);
        #pragma unroll
        for (int i = 0; i < NSTATE / 2; i++) { a0[i] = r0[i]; a1[i] = r1[i]; }
    }
    const float b0 = Bvec[n0];
    const float b1 = Bvec[n0 + 1];

    // c_0 = 0 (bit pattern of double 0.0 == two packed f32 zeros)
    c_sm[0][lane] = 0.0;
    __syncwarp();

    float* op = out + (size_t)bd * NSTATE + n0;
    int cur = 0;

    for (int t = 0; t < SEQ_LEN; t++) {
        const float f = f_sm[t];
        const double2* cs = reinterpret_cast<const double2*>(c_sm[cur]);

        // acc over m in packed pairs; 4 independent accumulator chains.
        double acc00 = 0.0, acc01 = 0.0, acc10 = 0.0, acc11 = 0.0;
        #pragma unroll
        for (int i = 0; i < 16; i++) {
            const double2 cv = cs[i];               // (c[4i],c[4i+1]) , (c[4i+2],c[4i+3])
            acc00 = fma2(a0[2 * i],     cv.x, acc00);
            acc01 = fma2(a0[2 * i + 1], cv.y, acc01);
            acc10 = fma2(a1[2 * i],     cv.x, acc10);
            acc11 = fma2(a1[2 * i + 1], cv.y, acc11);
        }
        const double s0 = add2(acc00, acc01);
        const double s1 = add2(acc10, acc11);
        float x0, y0, x1, y1;
        unpack2(s0, x0, y0);
        unpack2(s1, x1, y1);
        const float cn0 = fmaf(f, b0, x0 + y0);
        const float cn1 = fmaf(f, b1, x1 + y1);

        const double cpack = pack2(cn0, cn1);
        c_sm[cur ^ 1][lane] = cpack;                // publish new state
        __syncwarp();
        cur ^= 1;

        *reinterpret_cast<double*>(op) = cpack;     // coalesced 256B/warp store
        op += (size_t)BD_TOTAL * NSTATE;
    }
}

extern "C" void kernel_launch(void* const* d_in, const int* in_sizes, int n_in,
                              void* d_out, int out_size)
{
    const float* xin  = (const float*)d_in[0];  // (16,128,512)
    const float* Amat = (const float*)d_in[1];  // (64,64)
    const float* Bvec = (const float*)d_in[2];  // (64,)
    float* out = (float*)d_out;                 // (512,16,128,64)

    hippo_scan_kernel<<<BD_TOTAL, 32>>>(xin, Amat, Bvec, out);
}